// round 14
// baseline (speedup 1.0000x reference)
#include <cuda_runtime.h>
#include <cuda_fp16.h>
#include <mma.h>
#include <math.h>
#include <stdint.h>

#define N_NODES 10000
#define N_EDGES 128000
#define E_HALF  64000

// ---------------- scratch (device globals; no allocations allowed) ----------------
__device__ float g_P   [N_NODES*128];
__device__ float g_x1  [N_NODES*64];
__device__ float g_x2  [N_NODES*64];
__device__ float g_x3  [N_NODES*64];
__device__ float g_x4  [N_NODES*64];
__device__ float g_Eu  [(size_t)N_EDGES*64];   // conv2 edge_attr part (Wbig cols 64..127)
__device__ float g_M1  [(size_t)N_EDGES*64];
__device__ float g_M2  [(size_t)N_EDGES*64];
__device__ float g_M3  [(size_t)N_EDGES*64];
__device__ float g_M4  [(size_t)N_EDGES*64];
__device__ float g_W1n [260*128];
__device__ float g_Wbig[640*128];
__device__ float g_W2n [64*128];
__device__ float g_W3n [128*128];
__device__ float g_W4n [128*128];
__device__ float g_inv [N_NODES];
__device__ int   g_cnt [N_NODES];

// ---------------- fp16 split helpers ----------------
__device__ __forceinline__ void hsplit1(float v, __half& h, __half& l)
{
    h = __float2half_rn(v);
    l = __float2half_rn(v - __half2float(h));
}
__device__ __forceinline__ void hsplit_store4(__half* ph, __half* pl, float4 v)
{
    float vv[4] = { v.x, v.y, v.z, v.w };
#pragma unroll
    for (int i = 0; i < 4; i++) {
        __half h = __float2half_rn(vv[i]);
        ph[i] = h;
        pl[i] = __float2half_rn(vv[i] - __half2float(h));
    }
}

// =====================================================================
// 3-term split-fp16 WMMA GEMM with optional fused second GEMM.
//   stage1: C1[BM,BN] = op(A0|A1) @ B      (Ah@Bh + Al@Bh + Ah@Bl)
//   EPI 0: C = acc                                  (node P GEMMs; no stage2)
//   EPI 1: j>=64 -> Eu; j<64 -> H = relu(acc + Pgather + b1 + rot@rotW) -> smem
//   EPI 2: H = relu(acc + Eu + Pgather + b1) -> smem
//   EPI 3: H = relu(acc + Pgather + b1) -> smem
//   EPI>=1 stage2: M = H @ W2 + b2 ; Mout = M ; atomicAdd(xsum[row], M)
// =====================================================================
template<int BN, int EPI>
__global__ __launch_bounds__(256) void gemm_f(
    const float* __restrict__ A0, int ldA0, int K0,
    const float* __restrict__ A1, int ldA1, int K1, int reluA,
    const float* __restrict__ B, int ldB,
    const float* __restrict__ bias,
    float* __restrict__ C, int ldC, int M,
    const int* __restrict__ row, const int* __restrict__ col,
    const float* __restrict__ P, const float* __restrict__ E0u,
    const float* __restrict__ rot, const float* __restrict__ rotW,
    const float* __restrict__ W2, const float* __restrict__ b2,
    float* __restrict__ Mout, float* __restrict__ xsum)
{
    using namespace nvcuda;
    constexpr int BM = 64, BK = 32;
    constexpr int WN = BN / 4;
    constexpr int MT = 2, NT = WN / 16;
    constexpr int CS_BYTES = BM * BN * 4;       // >= stage1 tile bytes for BN=64/128

    extern __shared__ __align__(16) char dsm[];
    __shared__ int sRow[BM], sCol[BM];

    __half* Ah = (__half*)dsm;
    __half* Al = Ah + BM * BK;
    __half* Bh = Al + BM * BK;
    __half* Bl = Bh + BK * BN;
    float*  Cs = (float*)dsm;
    __half* Hh = (__half*)(dsm + CS_BYTES);     // EPI>=1: 64x64
    __half* Hl = Hh + 64 * 64;
    __half* W2h = (__half*)(dsm + CS_BYTES + 16384);
    __half* W2l = W2h + 64 * 64;

    const int tid  = threadIdx.x;
    const int warp = tid >> 5;
    const int wm   = warp >> 2, wn = warp & 3;
    const int m0   = blockIdx.x * BM;
    const int K    = K0 + K1;

    if (EPI > 0) {
        if (tid < BM) {
            int e = m0 + tid;
            sRow[tid] = (e < M && row) ? row[e] : 0;
            sCol[tid] = (e < M && col) ? col[e] : 0;
        }
        // preload W2 (64x64) split — separate smem region, no sync needed yet
        for (int idx = tid; idx < 64 * 64; idx += 256) {
            __half h, l; hsplit1(W2[idx], h, l);
            W2h[idx] = h; W2l[idx] = l;
        }
    }

    wmma::fragment<wmma::accumulator, 16, 16, 16, float> acc[MT][NT];
#pragma unroll
    for (int mi = 0; mi < MT; mi++)
#pragma unroll
        for (int ni = 0; ni < NT; ni++) wmma::fill_fragment(acc[mi][ni], 0.f);

    for (int kb = 0; kb < K; kb += BK) {
        // ---- A tile: 64 x 32 fp32 -> exact fp16 split ----
        {
            const int r  = tid >> 2;
            const int m  = m0 + r;
            const int cb = (tid & 3) * 8;
#pragma unroll
            for (int q = 0; q < 2; q++) {
                const int c  = cb + q * 4;
                const int kk = kb + c;
                float4 v = make_float4(0.f, 0.f, 0.f, 0.f);
                if (m < M && kk < K) {
                    v = (kk < K0) ? *(const float4*)(A0 + (size_t)m * ldA0 + kk)
                                  : *(const float4*)(A1 + (size_t)m * ldA1 + (kk - K0));
                }
                if (reluA) {
                    v.x = fmaxf(v.x, 0.f); v.y = fmaxf(v.y, 0.f);
                    v.z = fmaxf(v.z, 0.f); v.w = fmaxf(v.w, 0.f);
                }
                hsplit_store4(Ah + r * BK + c, Al + r * BK + c, v);
            }
        }
        // ---- B tile: 32 x BN fp32 -> fp16 split ----
        {
            constexpr int JP = BN / 4;
#pragma unroll
            for (int idx = tid; idx < BK * JP; idx += 256) {
                const int k = idx / JP, jc = idx % JP;
                const int kk = kb + k;
                float4 v = make_float4(0.f, 0.f, 0.f, 0.f);
                if (kk < K) v = *(const float4*)(B + (size_t)kk * ldB + jc * 4);
                hsplit_store4(Bh + k * BN + jc * 4, Bl + k * BN + jc * 4, v);
            }
        }
        __syncthreads();
#pragma unroll
        for (int ks = 0; ks < 2; ks++) {
            wmma::fragment<wmma::matrix_a, 16, 16, 16, __half, wmma::row_major> fah[MT], fal[MT];
            wmma::fragment<wmma::matrix_b, 16, 16, 16, __half, wmma::row_major> fbh[NT], fbl[NT];
#pragma unroll
            for (int mi = 0; mi < MT; mi++) {
                const int off = (wm * 32 + mi * 16) * BK + ks * 16;
                wmma::load_matrix_sync(fah[mi], Ah + off, BK);
                wmma::load_matrix_sync(fal[mi], Al + off, BK);
            }
#pragma unroll
            for (int ni = 0; ni < NT; ni++) {
                const int off = (ks * 16) * BN + wn * WN + ni * 16;
                wmma::load_matrix_sync(fbh[ni], Bh + off, BN);
                wmma::load_matrix_sync(fbl[ni], Bl + off, BN);
            }
#pragma unroll
            for (int mi = 0; mi < MT; mi++)
#pragma unroll
                for (int ni = 0; ni < NT; ni++) {
                    wmma::mma_sync(acc[mi][ni], fah[mi], fbh[ni], acc[mi][ni]);
                    wmma::mma_sync(acc[mi][ni], fal[mi], fbh[ni], acc[mi][ni]);
                    wmma::mma_sync(acc[mi][ni], fah[mi], fbl[ni], acc[mi][ni]);
                }
        }
        __syncthreads();
    }

    // ---- stage1 epilogue via smem C tile (tiles dead; reuse dsm) ----
#pragma unroll
    for (int mi = 0; mi < MT; mi++)
#pragma unroll
        for (int ni = 0; ni < NT; ni++)
            wmma::store_matrix_sync(Cs + (wm * 32 + mi * 16) * BN + wn * WN + ni * 16,
                                    acc[mi][ni], BN, wmma::mem_row_major);
    __syncthreads();

    for (int idx = tid; idx < BM * BN; idx += 256) {
        const int i = idx / BN, j = idx - i * BN;
        const int m = m0 + i;
        if (m >= M) continue;
        float v = Cs[idx];
        if (EPI == 0) {
            C[(size_t)m * ldC + j] = v;
        } else if (EPI == 1) {
            if (j >= 64) {
                C[(size_t)m * 64 + (j - 64)] = v;          // Eu compact
            } else {
                const int r = sRow[i], c = sCol[i];
                float h = v + P[r * 128 + j] + P[c * 128 + 64 + j] + bias[j];
#pragma unroll
                for (int kk = 0; kk < 4; kk++)
                    h += rot[(size_t)m * 4 + kk] * rotW[kk * 64 + j];
                h = fmaxf(h, 0.f);
                __half hh, hl; hsplit1(h, hh, hl);
                Hh[i * 64 + j] = hh; Hl[i * 64 + j] = hl;
            }
        } else { // EPI 2/3
            const int r = sRow[i], c = sCol[i];
            float h = v + P[r * 128 + j] + P[c * 128 + 64 + j] + bias[j];
            if (EPI == 2) h += E0u[(size_t)m * 64 + j];
            h = fmaxf(h, 0.f);
            __half hh, hl; hsplit1(h, hh, hl);
            Hh[i * 64 + j] = hh; Hl[i * 64 + j] = hl;
        }
    }

    if (EPI == 0) return;

    // ---- stage2: M = H @ W2 + b2 (64x64x64, 3-term) ----
    __syncthreads();
    {
        const int r0 = (warp & 3) * 16;
        const int c0 = (warp >> 2) * 32;
        wmma::fragment<wmma::accumulator, 16, 16, 16, float> acc2[2];
        wmma::fill_fragment(acc2[0], 0.f);
        wmma::fill_fragment(acc2[1], 0.f);
#pragma unroll
        for (int ks = 0; ks < 4; ks++) {
            wmma::fragment<wmma::matrix_a, 16, 16, 16, __half, wmma::row_major> fah, fal;
            wmma::load_matrix_sync(fah, Hh + r0 * 64 + ks * 16, 64);
            wmma::load_matrix_sync(fal, Hl + r0 * 64 + ks * 16, 64);
#pragma unroll
            for (int t = 0; t < 2; t++) {
                wmma::fragment<wmma::matrix_b, 16, 16, 16, __half, wmma::row_major> fbh, fbl;
                wmma::load_matrix_sync(fbh, W2h + (ks * 16) * 64 + c0 + t * 16, 64);
                wmma::load_matrix_sync(fbl, W2l + (ks * 16) * 64 + c0 + t * 16, 64);
                wmma::mma_sync(acc2[t], fah, fbh, acc2[t]);
                wmma::mma_sync(acc2[t], fal, fbh, acc2[t]);
                wmma::mma_sync(acc2[t], fah, fbl, acc2[t]);
            }
        }
        __syncthreads();   // Cs region free (stage1 epilogue done)
        wmma::store_matrix_sync(Cs + r0 * 64 + c0,      acc2[0], 64, wmma::mem_row_major);
        wmma::store_matrix_sync(Cs + r0 * 64 + c0 + 16, acc2[1], 64, wmma::mem_row_major);
    }
    __syncthreads();

    for (int idx = tid; idx < 64 * 64; idx += 256) {
        const int i = idx >> 6, j = idx & 63;
        const int m = m0 + i;
        if (m >= M) continue;
        float v = Cs[idx] + b2[j];
        Mout[(size_t)m * 64 + j] = v;
        atomicAdd(&xsum[sRow[i] * 64 + j], v);
    }
}

// ---------------- misc kernels ----------------
__global__ void pack_kernel(float* __restrict__ dst,
                            const float* __restrict__ srcA, int offA,
                            const float* __restrict__ srcB, int offB, int K)
{
    int idx = blockIdx.x * blockDim.x + threadIdx.x;
    if (idx >= K * 128) return;
    int k = idx >> 7, j = idx & 127;
    dst[idx] = (j < 64) ? srcA[(offA + k) * 64 + j]
                        : srcB[(offB + k) * 64 + (j - 64)];
}

__global__ void zero_f_kernel(float* p, long n)
{
    long i = (long)blockIdx.x * blockDim.x + threadIdx.x;
    if (i < n) p[i] = 0.f;
}
__global__ void zero_cnt_kernel()
{
    int i = blockIdx.x * blockDim.x + threadIdx.x;
    if (i < N_NODES) g_cnt[i] = 0;
}
__global__ void count_kernel(const int* __restrict__ row)
{
    int e = blockIdx.x * blockDim.x + threadIdx.x;
    if (e < N_EDGES) atomicAdd(&g_cnt[row[e]], 1);
}
__global__ void invdeg_kernel()
{
    int n = blockIdx.x * blockDim.x + threadIdx.x;
    if (n < N_NODES) g_inv[n] = 1.f / fmaxf((float)g_cnt[n], 1.f);
}
__global__ void finalize_kernel(float* __restrict__ x, int relu)
{
    int idx = blockIdx.x * blockDim.x + threadIdx.x;
    if (idx >= N_NODES * 64) return;
    int n = idx >> 6;
    float v = x[idx] * g_inv[n];
    x[idx] = relu ? fmaxf(v, 0.f) : v;
}

__global__ void node_head_kernel(const float* __restrict__ W,
                                 const float* __restrict__ b,
                                 float* __restrict__ out)
{
    int n = blockIdx.x * blockDim.x + threadIdx.x;
    if (n >= N_NODES) return;
    float y0 = b[0], y1 = b[1], y2 = b[2], y3 = b[3];
    const float* xr = g_x4 + (long)n * 64;
#pragma unroll 8
    for (int k = 0; k < 64; k++) {
        float xv = xr[k];
        y0 = fmaf(xv, W[k * 4 + 0], y0);
        y1 = fmaf(xv, W[k * 4 + 1], y1);
        y2 = fmaf(xv, W[k * 4 + 2], y2);
        y3 = fmaf(xv, W[k * 4 + 3], y3);
    }
    float s = y0 * y0 + y1 * y1 + y2 * y2 + y3 * y3;
    float r = 1.f / fmaxf(sqrtf(s), 1e-12f);
    out[n * 4 + 0] = y0 * r;
    out[n * 4 + 1] = y1 * r;
    out[n * 4 + 2] = y2 * r;
    out[n * 4 + 3] = y3 * r;
}

__global__ __launch_bounds__(256) void edge_head_kernel(
    const float* __restrict__ W1, const float* __restrict__ b1,
    const float* __restrict__ w2, const float* __restrict__ b2,
    float* __restrict__ out)
{
    __shared__ float sW[64 * 32];
    __shared__ float sb[32];
    int tid = threadIdx.x;
    for (int i = tid; i < 64 * 32; i += 256) sW[i] = W1[i];
    if (tid < 32) sb[tid] = b1[tid];
    __syncthreads();
    int lane = tid & 31, w = tid >> 5;
    int e = blockIdx.x * 8 + w;
    if (e >= E_HALF) return;
    const float* h0 = g_M4 + (long)e * 64;
    const float* h1 = g_M4 + (long)(e + E_HALF) * 64;
    float t = sb[lane];
#pragma unroll 8
    for (int k = 0; k < 64; k++) {
        float h = h0[k] + h1[k];
        t = fmaf(h, sW[k * 32 + lane], t);
    }
    float r = fmaxf(t, 0.f) * w2[lane];
#pragma unroll
    for (int off = 16; off; off >>= 1) r += __shfl_down_sync(0xffffffffu, r, off);
    if (lane == 0) out[e] = r + b2[0];
}

// ---------------- host orchestration ----------------
template <class T>
static void* symaddr_(T& s)
{
    void* p = nullptr;
    cudaGetSymbolAddress(&p, s);
    return p;
}
#define SYM(x) symaddr_(x)

extern "C" void kernel_launch(void* const* d_in, const int* in_sizes, int n_in,
                              void* d_out, int out_size)
{
    (void)in_sizes; (void)n_in; (void)out_size;
    const float* x_org = (const float*)d_in[0];
    const float* x_rot = (const float*)d_in[1];
    const int*   eidx  = (const int*)  d_in[2];
    const float* eattr = (const float*)d_in[3];
    const float* erot  = (const float*)d_in[4];
    const float* c1_w1 = (const float*)d_in[5];  const float* c1_b1 = (const float*)d_in[6];
    const float* c1_w2 = (const float*)d_in[7];  const float* c1_b2 = (const float*)d_in[8];
    const float* c2_w1 = (const float*)d_in[9];  const float* c2_b1 = (const float*)d_in[10];
    const float* c2_w2 = (const float*)d_in[11]; const float* c2_b2 = (const float*)d_in[12];
    const float* c3_w1 = (const float*)d_in[13]; const float* c3_b1 = (const float*)d_in[14];
    const float* c3_w2 = (const float*)d_in[15]; const float* c3_b2 = (const float*)d_in[16];
    const float* c4_w1 = (const float*)d_in[17]; const float* c4_b1 = (const float*)d_in[18];
    const float* c4_w2 = (const float*)d_in[19]; const float* c4_b2 = (const float*)d_in[20];
    const float* lin1_w = (const float*)d_in[21]; const float* lin1_b = (const float*)d_in[22];
    const float* efc_w1 = (const float*)d_in[23]; const float* efc_b1 = (const float*)d_in[24];
    const float* efc_w2 = (const float*)d_in[25]; const float* efc_b2 = (const float*)d_in[26];
    float* out = (float*)d_out;

    const int* row = eidx;
    const int* col = eidx + N_EDGES;

    float *P  = (float*)SYM(g_P);
    float *x1 = (float*)SYM(g_x1), *x2 = (float*)SYM(g_x2);
    float *x3 = (float*)SYM(g_x3), *x4 = (float*)SYM(g_x4);
    float *Eu = (float*)SYM(g_Eu);
    float *M1 = (float*)SYM(g_M1), *M2 = (float*)SYM(g_M2);
    float *M3 = (float*)SYM(g_M3), *M4 = (float*)SYM(g_M4);
    float *W1n = (float*)SYM(g_W1n), *Wbig = (float*)SYM(g_Wbig);
    float *W2n = (float*)SYM(g_W2n);
    float *W3n = (float*)SYM(g_W3n), *W4n = (float*)SYM(g_W4n);

    const int GE = N_EDGES / 64;               // 2000
    const int GN = (N_NODES + 63) / 64;        // 157
    const int ZB = (N_NODES * 64 + 255) / 256;
    const float* NF = nullptr;
    const int*   NI = nullptr;

    cudaFuncSetAttribute(gemm_f<128, 0>, cudaFuncAttributeMaxDynamicSharedMemorySize, 32768);
    cudaFuncSetAttribute(gemm_f<128, 1>, cudaFuncAttributeMaxDynamicSharedMemorySize, 65536);
    cudaFuncSetAttribute(gemm_f<64, 2>,  cudaFuncAttributeMaxDynamicSharedMemorySize, 49152);
    cudaFuncSetAttribute(gemm_f<64, 3>,  cudaFuncAttributeMaxDynamicSharedMemorySize, 49152);

    // ---------- prep ----------
    pack_kernel<<<(260 * 128 + 255) / 256, 256>>>(W1n,  c1_w1, 0,   c1_w1, 260, 260);
    pack_kernel<<<(640 * 128 + 255) / 256, 256>>>(Wbig, c1_w1, 520, c2_w1, 128, 640);
    pack_kernel<<<(64  * 128 + 255) / 256, 256>>>(W2n, c2_w1, 0, c2_w1, 64,  64);
    pack_kernel<<<(128 * 128 + 255) / 256, 256>>>(W3n, c3_w1, 0, c3_w1, 128, 128);
    pack_kernel<<<(128 * 128 + 255) / 256, 256>>>(W4n, c4_w1, 0, c4_w1, 128, 128);
    zero_cnt_kernel<<<(N_NODES + 255) / 256, 256>>>();
    count_kernel<<<(N_EDGES + 255) / 256, 256>>>(row);
    invdeg_kernel<<<(N_NODES + 255) / 256, 256>>>();
    zero_f_kernel<<<ZB, 256>>>(x1, (long)N_NODES * 64);
    zero_f_kernel<<<ZB, 256>>>(x2, (long)N_NODES * 64);
    zero_f_kernel<<<ZB, 256>>>(x3, (long)N_NODES * 64);
    zero_f_kernel<<<ZB, 256>>>(x4, (long)N_NODES * 64);

    // ================= conv1 =================
    gemm_f<128, 0><<<GN, 256, 32768>>>(x_org, 256, 256, x_rot, 4, 4, 0,
                                       W1n, 128, NF, P, 128, N_NODES,
                                       NI, NI, NF, NF, NF, NF, NF, NF, nullptr, nullptr);
    // big fused: Eu + H(smem) + M1 = H@c1_w2 + scatter(x1)
    gemm_f<128, 1><<<GE, 256, 65536>>>(eattr, 640, 640, NF, 0, 0, 0,
                                       Wbig, 128, c1_b1, Eu, 128, N_EDGES,
                                       row, col, P, NF, erot, c1_w1 + 1160 * 64,
                                       c1_w2, c1_b2, M1, x1);
    finalize_kernel<<<ZB, 256>>>(x1, 0);

    // ================= conv2 =================
    gemm_f<128, 0><<<GN, 256, 32768>>>(x1, 64, 64, NF, 0, 0, 0,
                                       W2n, 128, NF, P, 128, N_NODES,
                                       NI, NI, NF, NF, NF, NF, NF, NF, nullptr, nullptr);
    gemm_f<64, 2><<<GE, 256, 49152>>>(M1, 64, 64, NF, 0, 0, 1,
                                      c2_w1 + 768 * 64, 64, c2_b1, nullptr, 64, N_EDGES,
                                      row, col, P, Eu, NF, NF,
                                      c2_w2, c2_b2, M2, x2);
    finalize_kernel<<<ZB, 256>>>(x2, 1);

    // ================= conv3 =================
    gemm_f<128, 0><<<GN, 256, 32768>>>(x2, 64, 64, x1, 64, 64, 0,
                                       W3n, 128, NF, P, 128, N_NODES,
                                       NI, NI, NF, NF, NF, NF, NF, NF, nullptr, nullptr);
    gemm_f<64, 3><<<GE, 256, 49152>>>(M2, 64, 64, M1, 64, 64, 1,
                                      c3_w1 + 256 * 64, 64, c3_b1, nullptr, 64, N_EDGES,
                                      row, col, P, NF, NF, NF,
                                      c3_w2, c3_b2, M3, x3);
    finalize_kernel<<<ZB, 256>>>(x3, 1);

    // ================= conv4 =================
    gemm_f<128, 0><<<GN, 256, 32768>>>(x3, 64, 64, x2, 64, 64, 0,
                                       W4n, 128, NF, P, 128, N_NODES,
                                       NI, NI, NF, NF, NF, NF, NF, NF, nullptr, nullptr);
    gemm_f<64, 3><<<GE, 256, 49152>>>(M3, 64, 64, M2, 64, 64, 1,
                                      c4_w1 + 256 * 64, 64, c4_b1, nullptr, 64, N_EDGES,
                                      row, col, P, NF, NF, NF,
                                      c4_w2, c4_b2, M4, x4);
    finalize_kernel<<<ZB, 256>>>(x4, 1);

    // ================= heads =================
    node_head_kernel<<<(N_NODES + 127) / 128, 128>>>(lin1_w, lin1_b, out);
    edge_head_kernel<<<(E_HALF + 7) / 8, 256>>>(efc_w1, efc_b1, efc_w2, efc_b2,
                                                out + N_NODES * 4);
}

// round 15
// speedup vs baseline: 1.0316x; 1.0316x over previous
#include <cuda_runtime.h>
#include <cuda_fp16.h>
#include <mma.h>
#include <math.h>
#include <stdint.h>

#define N_NODES 10000
#define N_EDGES 128000
#define E_HALF  64000

// ---------------- scratch (device globals; no allocations allowed) ----------------
__device__ float g_P   [N_NODES*128];
__device__ float g_x1  [N_NODES*64];
__device__ float g_x2  [N_NODES*64];
__device__ float g_x3  [N_NODES*64];
__device__ float g_x4  [N_NODES*64];
__device__ float g_Ebig[(size_t)N_EDGES*128];
__device__ float g_M1  [(size_t)N_EDGES*64];
__device__ float g_M2  [(size_t)N_EDGES*64];
__device__ float g_M3  [(size_t)N_EDGES*64];
__device__ float g_M4  [(size_t)N_EDGES*64];
__device__ float g_H   [(size_t)N_EDGES*64];
__device__ float g_W1n [260*128];
__device__ float g_Wbig[640*128];
__device__ float g_W2n [64*128];
__device__ float g_W3n [128*128];
__device__ float g_W4n [128*128];
__device__ float g_inv [N_NODES];
__device__ int   g_cnt [N_NODES];

// ---------------- fp16 split helpers ----------------
__device__ __forceinline__ void hsplit_store4(__half* ph, __half* pl, float4 v)
{
    float vv[4] = { v.x, v.y, v.z, v.w };
#pragma unroll
    for (int i = 0; i < 4; i++) {
        __half h = __float2half_rn(vv[i]);
        ph[i] = h;
        pl[i] = __float2half_rn(vv[i] - __half2float(h));
    }
}

// =====================================================================
// 2.5-term split-fp16 WMMA GEMM:  C[M,BN] = op(A0|A1) @ B (+bias)
//   A logically [M, K0+K1] fp32 row-major via two pointers, optional relu.
//   B fp32 row-major [K, ldB].
//   Main term Ah@Bh -> fp32 accumulator.
//   Corrections Al@Bh + Ah@Bl -> SHARED fp16 accumulator (2x HMMA rate).
//   C = accF + float(accH).  (error ~2^-22-scale; AlBl dropped)
// EPI modes (identical to R6):
//   0: C = acc                                          (node P GEMMs)
//   1: conv1-big: j>=64 -> C(=Ebig, ldC=128); j<64 -> Hout = relu(acc+Pgather+bias+rot@rotW)
//   2: C = relu(acc + Ebig[:,64+j] + Pgather + bias)    (conv2 hidden)
//   3: C = relu(acc + Pgather + bias)                   (conv3/4 hidden)
//   4: v = acc + bias; C = v; atomicAdd(xsum[row], v)   (M GEMM + scatter)
// =====================================================================
template<int BN, int EPI>
__global__ __launch_bounds__(256) void gemm_h25(
    const float* __restrict__ A0, int ldA0, int K0,
    const float* __restrict__ A1, int ldA1, int K1, int reluA,
    const float* __restrict__ B, int ldB,
    const float* __restrict__ bias,
    float* __restrict__ C, int ldC, int M,
    const int* __restrict__ row, const int* __restrict__ col,
    const float* __restrict__ P, const float* __restrict__ E0,
    const float* __restrict__ rot, const float* __restrict__ rotW,
    float* __restrict__ xsum, float* __restrict__ Hout)
{
    using namespace nvcuda;
    constexpr int BM = 64, BK = 32;
    constexpr int WN = BN / 4;
    constexpr int MT = 2, NT = WN / 16;
    constexpr int TILE_BYTES = (2 * BM * BK + 2 * BK * BN) * 2;
    constexpr int CS_BYTES   = BM * BN * 4;
    constexpr int R0 = TILE_BYTES > CS_BYTES ? TILE_BYTES : CS_BYTES;  // region 0

    extern __shared__ __align__(16) char dsm[];
    __shared__ int sRow[BM], sCol[BM];
    __half* Ah = (__half*)dsm;
    __half* Al = Ah + BM * BK;
    __half* Bh = Al + BM * BK;
    __half* Bl = Bh + BK * BN;
    float*  Cs = (float*)dsm;
    __half* Ch = (__half*)(dsm + R0);           // half-acc correction tile

    const int tid  = threadIdx.x;
    const int warp = tid >> 5;
    const int wm   = warp >> 2, wn = warp & 3;
    const int m0   = blockIdx.x * BM;
    const int K    = K0 + K1;

    if (EPI > 0 && tid < BM) {
        int e = m0 + tid;
        sRow[tid] = (e < M && row) ? row[e] : 0;
        sCol[tid] = (e < M && col) ? col[e] : 0;
    }

    wmma::fragment<wmma::accumulator, 16, 16, 16, float>  accF[MT][NT];
    wmma::fragment<wmma::accumulator, 16, 16, 16, __half> accH[MT][NT];
#pragma unroll
    for (int mi = 0; mi < MT; mi++)
#pragma unroll
        for (int ni = 0; ni < NT; ni++) {
            wmma::fill_fragment(accF[mi][ni], 0.f);
            wmma::fill_fragment(accH[mi][ni], __float2half(0.f));
        }

    for (int kb = 0; kb < K; kb += BK) {
        // ---- A tile: 64 x 32 fp32 -> exact fp16 split ----
        {
            const int r  = tid >> 2;
            const int m  = m0 + r;
            const int cb = (tid & 3) * 8;
#pragma unroll
            for (int q = 0; q < 2; q++) {
                const int c  = cb + q * 4;
                const int kk = kb + c;
                float4 v = make_float4(0.f, 0.f, 0.f, 0.f);
                if (m < M && kk < K) {
                    v = (kk < K0) ? *(const float4*)(A0 + (size_t)m * ldA0 + kk)
                                  : *(const float4*)(A1 + (size_t)m * ldA1 + (kk - K0));
                }
                if (reluA) {
                    v.x = fmaxf(v.x, 0.f); v.y = fmaxf(v.y, 0.f);
                    v.z = fmaxf(v.z, 0.f); v.w = fmaxf(v.w, 0.f);
                }
                hsplit_store4(Ah + r * BK + c, Al + r * BK + c, v);
            }
        }
        // ---- B tile: 32 x BN fp32 -> fp16 split ----
        {
            constexpr int JP = BN / 4;
#pragma unroll
            for (int idx = tid; idx < BK * JP; idx += 256) {
                const int k = idx / JP, jc = idx % JP;
                const int kk = kb + k;
                float4 v = make_float4(0.f, 0.f, 0.f, 0.f);
                if (kk < K) v = *(const float4*)(B + (size_t)kk * ldB + jc * 4);
                hsplit_store4(Bh + k * BN + jc * 4, Bl + k * BN + jc * 4, v);
            }
        }
        __syncthreads();
#pragma unroll
        for (int ks = 0; ks < 2; ks++) {
            wmma::fragment<wmma::matrix_a, 16, 16, 16, __half, wmma::row_major> fah[MT], fal[MT];
            wmma::fragment<wmma::matrix_b, 16, 16, 16, __half, wmma::row_major> fbh[NT], fbl[NT];
#pragma unroll
            for (int mi = 0; mi < MT; mi++) {
                const int off = (wm * 32 + mi * 16) * BK + ks * 16;
                wmma::load_matrix_sync(fah[mi], Ah + off, BK);
                wmma::load_matrix_sync(fal[mi], Al + off, BK);
            }
#pragma unroll
            for (int ni = 0; ni < NT; ni++) {
                const int off = (ks * 16) * BN + wn * WN + ni * 16;
                wmma::load_matrix_sync(fbh[ni], Bh + off, BN);
                wmma::load_matrix_sync(fbl[ni], Bl + off, BN);
            }
#pragma unroll
            for (int mi = 0; mi < MT; mi++)
#pragma unroll
                for (int ni = 0; ni < NT; ni++) {
                    wmma::mma_sync(accF[mi][ni], fah[mi], fbh[ni], accF[mi][ni]);  // main, fp32 acc
                    wmma::mma_sync(accH[mi][ni], fal[mi], fbh[ni], accH[mi][ni]);  // corr, fp16 acc
                    wmma::mma_sync(accH[mi][ni], fah[mi], fbl[ni], accH[mi][ni]);  // corr, fp16 acc
                }
        }
        __syncthreads();
    }

    // ---- epilogue: combine fp32 main + fp16 correction via smem ----
#pragma unroll
    for (int mi = 0; mi < MT; mi++)
#pragma unroll
        for (int ni = 0; ni < NT; ni++) {
            const int off = (wm * 32 + mi * 16) * BN + wn * WN + ni * 16;
            wmma::store_matrix_sync(Cs + off, accF[mi][ni], BN, wmma::mem_row_major);
            wmma::store_matrix_sync(Ch + off, accH[mi][ni], BN, wmma::mem_row_major);
        }
    __syncthreads();

    for (int idx = tid; idx < BM * BN; idx += 256) {
        const int i = idx / BN, j = idx - i * BN;
        const int m = m0 + i;
        if (m >= M) continue;
        float v = Cs[idx] + __half2float(Ch[idx]);
        if (EPI == 0) {
            C[(size_t)m * ldC + j] = v;
        } else if (EPI == 1) {
            if (j >= 64) {
                C[(size_t)m * ldC + j] = v;                 // Ebig upper half
            } else {
                const int r = sRow[i], c = sCol[i];
                float h = v + P[r * 128 + j] + P[c * 128 + 64 + j] + bias[j];
#pragma unroll
                for (int kk = 0; kk < 4; kk++)
                    h += rot[(size_t)m * 4 + kk] * rotW[kk * 64 + j];
                Hout[(size_t)m * 64 + j] = fmaxf(h, 0.f);
            }
        } else if (EPI == 2 || EPI == 3) {
            const int r = sRow[i], c = sCol[i];
            float h = v + P[r * 128 + j] + P[c * 128 + 64 + j] + bias[j];
            if (EPI == 2) h += E0[(size_t)m * 128 + 64 + j];
            C[(size_t)m * 64 + j] = fmaxf(h, 0.f);
        } else { // EPI == 4
            v += bias[j];
            C[(size_t)m * 64 + j] = v;
            atomicAdd(&xsum[sRow[i] * 64 + j], v);
        }
    }
}

// ---------------- misc kernels (R6 verbatim) ----------------
__global__ void pack_kernel(float* __restrict__ dst,
                            const float* __restrict__ srcA, int offA,
                            const float* __restrict__ srcB, int offB, int K)
{
    int idx = blockIdx.x * blockDim.x + threadIdx.x;
    if (idx >= K * 128) return;
    int k = idx >> 7, j = idx & 127;
    dst[idx] = (j < 64) ? srcA[(offA + k) * 64 + j]
                        : srcB[(offB + k) * 64 + (j - 64)];
}

__global__ void zero_f_kernel(float* p, long n)
{
    long i = (long)blockIdx.x * blockDim.x + threadIdx.x;
    if (i < n) p[i] = 0.f;
}
__global__ void zero_cnt_kernel()
{
    int i = blockIdx.x * blockDim.x + threadIdx.x;
    if (i < N_NODES) g_cnt[i] = 0;
}
__global__ void count_kernel(const int* __restrict__ row)
{
    int e = blockIdx.x * blockDim.x + threadIdx.x;
    if (e < N_EDGES) atomicAdd(&g_cnt[row[e]], 1);
}
__global__ void invdeg_kernel()
{
    int n = blockIdx.x * blockDim.x + threadIdx.x;
    if (n < N_NODES) g_inv[n] = 1.f / fmaxf((float)g_cnt[n], 1.f);
}
__global__ void finalize_kernel(float* __restrict__ x, int relu)
{
    int idx = blockIdx.x * blockDim.x + threadIdx.x;
    if (idx >= N_NODES * 64) return;
    int n = idx >> 6;
    float v = x[idx] * g_inv[n];
    x[idx] = relu ? fmaxf(v, 0.f) : v;
}

__global__ void node_head_kernel(const float* __restrict__ W,
                                 const float* __restrict__ b,
                                 float* __restrict__ out)
{
    int n = blockIdx.x * blockDim.x + threadIdx.x;
    if (n >= N_NODES) return;
    float y0 = b[0], y1 = b[1], y2 = b[2], y3 = b[3];
    const float* xr = g_x4 + (long)n * 64;
#pragma unroll 8
    for (int k = 0; k < 64; k++) {
        float xv = xr[k];
        y0 = fmaf(xv, W[k * 4 + 0], y0);
        y1 = fmaf(xv, W[k * 4 + 1], y1);
        y2 = fmaf(xv, W[k * 4 + 2], y2);
        y3 = fmaf(xv, W[k * 4 + 3], y3);
    }
    float s = y0 * y0 + y1 * y1 + y2 * y2 + y3 * y3;
    float r = 1.f / fmaxf(sqrtf(s), 1e-12f);
    out[n * 4 + 0] = y0 * r;
    out[n * 4 + 1] = y1 * r;
    out[n * 4 + 2] = y2 * r;
    out[n * 4 + 3] = y3 * r;
}

__global__ __launch_bounds__(256) void edge_head_kernel(
    const float* __restrict__ W1, const float* __restrict__ b1,
    const float* __restrict__ w2, const float* __restrict__ b2,
    float* __restrict__ out)
{
    __shared__ float sW[64 * 32];
    __shared__ float sb[32];
    int tid = threadIdx.x;
    for (int i = tid; i < 64 * 32; i += 256) sW[i] = W1[i];
    if (tid < 32) sb[tid] = b1[tid];
    __syncthreads();
    int lane = tid & 31, w = tid >> 5;
    int e = blockIdx.x * 8 + w;
    if (e >= E_HALF) return;
    const float* h0 = g_M4 + (long)e * 64;
    const float* h1 = g_M4 + (long)(e + E_HALF) * 64;
    float t = sb[lane];
#pragma unroll 8
    for (int k = 0; k < 64; k++) {
        float h = h0[k] + h1[k];
        t = fmaf(h, sW[k * 32 + lane], t);
    }
    float r = fmaxf(t, 0.f) * w2[lane];
#pragma unroll
    for (int off = 16; off; off >>= 1) r += __shfl_down_sync(0xffffffffu, r, off);
    if (lane == 0) out[e] = r + b2[0];
}

// ---------------- host orchestration (R6 verbatim, new kernel + dyn smem) ----------------
template <class T>
static void* symaddr_(T& s)
{
    void* p = nullptr;
    cudaGetSymbolAddress(&p, s);
    return p;
}
#define SYM(x) symaddr_(x)

extern "C" void kernel_launch(void* const* d_in, const int* in_sizes, int n_in,
                              void* d_out, int out_size)
{
    (void)in_sizes; (void)n_in; (void)out_size;
    const float* x_org = (const float*)d_in[0];
    const float* x_rot = (const float*)d_in[1];
    const int*   eidx  = (const int*)  d_in[2];
    const float* eattr = (const float*)d_in[3];
    const float* erot  = (const float*)d_in[4];
    const float* c1_w1 = (const float*)d_in[5];  const float* c1_b1 = (const float*)d_in[6];
    const float* c1_w2 = (const float*)d_in[7];  const float* c1_b2 = (const float*)d_in[8];
    const float* c2_w1 = (const float*)d_in[9];  const float* c2_b1 = (const float*)d_in[10];
    const float* c2_w2 = (const float*)d_in[11]; const float* c2_b2 = (const float*)d_in[12];
    const float* c3_w1 = (const float*)d_in[13]; const float* c3_b1 = (const float*)d_in[14];
    const float* c3_w2 = (const float*)d_in[15]; const float* c3_b2 = (const float*)d_in[16];
    const float* c4_w1 = (const float*)d_in[17]; const float* c4_b1 = (const float*)d_in[18];
    const float* c4_w2 = (const float*)d_in[19]; const float* c4_b2 = (const float*)d_in[20];
    const float* lin1_w = (const float*)d_in[21]; const float* lin1_b = (const float*)d_in[22];
    const float* efc_w1 = (const float*)d_in[23]; const float* efc_b1 = (const float*)d_in[24];
    const float* efc_w2 = (const float*)d_in[25]; const float* efc_b2 = (const float*)d_in[26];
    float* out = (float*)d_out;

    const int* row = eidx;
    const int* col = eidx + N_EDGES;

    float *P    = (float*)SYM(g_P);
    float *x1   = (float*)SYM(g_x1), *x2 = (float*)SYM(g_x2);
    float *x3   = (float*)SYM(g_x3), *x4 = (float*)SYM(g_x4);
    float *Ebig = (float*)SYM(g_Ebig), *H = (float*)SYM(g_H);
    float *M1   = (float*)SYM(g_M1), *M2 = (float*)SYM(g_M2);
    float *M3   = (float*)SYM(g_M3), *M4 = (float*)SYM(g_M4);
    float *W1n  = (float*)SYM(g_W1n), *Wbig = (float*)SYM(g_Wbig);
    float *W2n  = (float*)SYM(g_W2n);
    float *W3n  = (float*)SYM(g_W3n), *W4n = (float*)SYM(g_W4n);

    const int GE = N_EDGES / 64;               // 2000
    const int GN = (N_NODES + 63) / 64;        // 157
    const int ZB = (N_NODES * 64 + 255) / 256;
    const int SM128 = 32768 + 16384;           // Cs(32K) + Ch(16K)
    const int SM64  = 16384 + 8192;            // Cs(16K) + Ch(8K)
    const float* NF = nullptr;
    const int*   NI = nullptr;

    cudaFuncSetAttribute(gemm_h25<128, 0>, cudaFuncAttributeMaxDynamicSharedMemorySize, SM128);
    cudaFuncSetAttribute(gemm_h25<128, 1>, cudaFuncAttributeMaxDynamicSharedMemorySize, SM128);
    cudaFuncSetAttribute(gemm_h25<64, 2>,  cudaFuncAttributeMaxDynamicSharedMemorySize, SM64);
    cudaFuncSetAttribute(gemm_h25<64, 3>,  cudaFuncAttributeMaxDynamicSharedMemorySize, SM64);
    cudaFuncSetAttribute(gemm_h25<64, 4>,  cudaFuncAttributeMaxDynamicSharedMemorySize, SM64);

    // --- prep (R6 order) ---
    pack_kernel<<<(260 * 128 + 255) / 256, 256>>>(W1n,  c1_w1, 0,   c1_w1, 260, 260);
    pack_kernel<<<(640 * 128 + 255) / 256, 256>>>(Wbig, c1_w1, 520, c2_w1, 128, 640);
    pack_kernel<<<(64  * 128 + 255) / 256, 256>>>(W2n,  c2_w1, 0,   c2_w1, 64,  64);
    pack_kernel<<<(128 * 128 + 255) / 256, 256>>>(W3n,  c3_w1, 0,   c3_w1, 128, 128);
    pack_kernel<<<(128 * 128 + 255) / 256, 256>>>(W4n,  c4_w1, 0,   c4_w1, 128, 128);
    zero_cnt_kernel<<<(N_NODES + 255) / 256, 256>>>();
    count_kernel<<<(N_EDGES + 255) / 256, 256>>>(row);
    invdeg_kernel<<<(N_NODES + 255) / 256, 256>>>();
    zero_f_kernel<<<ZB, 256>>>(x1, (long)N_NODES * 64);
    zero_f_kernel<<<ZB, 256>>>(x2, (long)N_NODES * 64);
    zero_f_kernel<<<ZB, 256>>>(x3, (long)N_NODES * 64);
    zero_f_kernel<<<ZB, 256>>>(x4, (long)N_NODES * 64);

    // ================= conv1 =================
    gemm_h25<128, 0><<<GN, 256, SM128>>>(x_org, 256, 256, x_rot, 4, 4, 0,
                                         W1n, 128, NF, P, 128, N_NODES,
                                         NI, NI, NF, NF, NF, NF, nullptr, nullptr);
    gemm_h25<128, 1><<<GE, 256, SM128>>>(eattr, 640, 640, NF, 0, 0, 0,
                                         Wbig, 128, c1_b1, Ebig, 128, N_EDGES,
                                         row, col, P, NF, erot, c1_w1 + 1160 * 64, nullptr, H);
    gemm_h25<64, 4><<<GE, 256, SM64>>>(H, 64, 64, NF, 0, 0, 0,
                                       c1_w2, 64, c1_b2, M1, 64, N_EDGES,
                                       row, NI, NF, NF, NF, NF, x1, nullptr);
    finalize_kernel<<<ZB, 256>>>(x1, 0);

    // ================= conv2 =================
    gemm_h25<128, 0><<<GN, 256, SM128>>>(x1, 64, 64, NF, 0, 0, 0,
                                         W2n, 128, NF, P, 128, N_NODES,
                                         NI, NI, NF, NF, NF, NF, nullptr, nullptr);
    gemm_h25<64, 2><<<GE, 256, SM64>>>(M1, 64, 64, NF, 0, 0, 1,
                                       c2_w1 + 768 * 64, 64, c2_b1, H, 64, N_EDGES,
                                       row, col, P, Ebig, NF, NF, nullptr, nullptr);
    gemm_h25<64, 4><<<GE, 256, SM64>>>(H, 64, 64, NF, 0, 0, 0,
                                       c2_w2, 64, c2_b2, M2, 64, N_EDGES,
                                       row, NI, NF, NF, NF, NF, x2, nullptr);
    finalize_kernel<<<ZB, 256>>>(x2, 1);

    // ================= conv3 =================
    gemm_h25<128, 0><<<GN, 256, SM128>>>(x2, 64, 64, x1, 64, 64, 0,
                                         W3n, 128, NF, P, 128, N_NODES,
                                         NI, NI, NF, NF, NF, NF, nullptr, nullptr);
    gemm_h25<64, 3><<<GE, 256, SM64>>>(M2, 64, 64, M1, 64, 64, 1,
                                       c3_w1 + 256 * 64, 64, c3_b1, H, 64, N_EDGES,
                                       row, col, P, NF, NF, NF, nullptr, nullptr);
    gemm_h25<64, 4><<<GE, 256, SM64>>>(H, 64, 64, NF, 0, 0, 0,
                                       c3_w2, 64, c3_b2, M3, 64, N_EDGES,
                                       row, NI, NF, NF, NF, NF, x3, nullptr);
    finalize_kernel<<<ZB, 256>>>(x3, 1);

    // ================= conv4 =================
    gemm_h25<128, 0><<<GN, 256, SM128>>>(x3, 64, 64, x2, 64, 64, 0,
                                         W4n, 128, NF, P, 128, N_NODES,
                                         NI, NI, NF, NF, NF, NF, nullptr, nullptr);
    gemm_h25<64, 3><<<GE, 256, SM64>>>(M3, 64, 64, M2, 64, 64, 1,
                                       c4_w1 + 256 * 64, 64, c4_b1, H, 64, N_EDGES,
                                       row, col, P, NF, NF, NF, nullptr, nullptr);
    gemm_h25<64, 4><<<GE, 256, SM64>>>(H, 64, 64, NF, 0, 0, 0,
                                       c4_w2, 64, c4_b2, M4, 64, N_EDGES,
                                       row, NI, NF, NF, NF, NF, x4, nullptr);
    finalize_kernel<<<ZB, 256>>>(x4, 1);

    // ================= heads =================
    node_head_kernel<<<(N_NODES + 127) / 128, 128>>>(lin1_w, lin1_b, out);
    edge_head_kernel<<<(E_HALF + 7) / 8, 256>>>(efc_w1, efc_b1, efc_w2, efc_b2,
                                                out + N_NODES * 4);
}

// round 16
// speedup vs baseline: 1.0471x; 1.0150x over previous
#include <cuda_runtime.h>
#include <cuda_fp16.h>
#include <mma.h>
#include <math.h>
#include <stdint.h>

#define N_NODES 10000
#define N_EDGES 128000
#define E_HALF  64000

// ---------------- scratch (device globals; no allocations allowed) ----------------
__device__ float g_P   [N_NODES*128];
__device__ float g_x1  [N_NODES*64];
__device__ float g_x2  [N_NODES*64];
__device__ float g_x3  [N_NODES*64];
__device__ float g_x4  [N_NODES*64];
__device__ float g_Ebig[(size_t)N_EDGES*128];
__device__ float g_M1  [(size_t)N_EDGES*64];
__device__ float g_M2  [(size_t)N_EDGES*64];
__device__ float g_M3  [(size_t)N_EDGES*64];
__device__ float g_M4  [(size_t)N_EDGES*64];
__device__ float g_H   [(size_t)N_EDGES*64];
__device__ float g_W1n [260*128];
__device__ float g_Wbig[640*128];
__device__ float g_W2n [64*128];
__device__ float g_W3n [128*128];
__device__ float g_W4n [128*128];
__device__ float g_inv [N_NODES];
__device__ int   g_cnt [N_NODES];

// ---------------- fp16 split helpers ----------------
__device__ __forceinline__ void hsplit_store4(__half* ph, __half* pl, float4 v)
{
    float vv[4] = { v.x, v.y, v.z, v.w };
#pragma unroll
    for (int i = 0; i < 4; i++) {
        __half h = __float2half_rn(vv[i]);
        ph[i] = h;
        pl[i] = __float2half_rn(vv[i] - __half2float(h));
    }
}

// =====================================================================
// 3-term split-fp16 WMMA GEMM, BM=128, high fragment reuse.
//   C[M,BN] = op(A0|A1) @ B (+bias);  C = Ah@Bh + Al@Bh + Ah@Bl.
//   Warps 4x2 (wm 0-3 rows of 32; wn 0-1 cols of BN/2); MT=2, NT=BN/32.
//   Epilogue: BN=64 single pass; BN=128 two 64-col passes (Cs = 128x64).
// EPI modes (identical semantics to R6):
//   0: C = acc                                          (node P GEMMs)
//   1: conv1-big: j>=64 -> C(=Ebig, ldC=128); j<64 -> Hout = relu(acc+Pgather+bias+rot@rotW)
//   2: C = relu(acc + Ebig[:,64+j] + Pgather + bias)    (conv2 hidden)
//   3: C = relu(acc + Pgather + bias)                   (conv3/4 hidden)
//   4: v = acc + bias; C = v; atomicAdd(xsum[row], v)   (M GEMM + scatter)
// =====================================================================
template<int BN, int EPI>
__global__ __launch_bounds__(256, 2) void gemm_r(
    const float* __restrict__ A0, int ldA0, int K0,
    const float* __restrict__ A1, int ldA1, int K1, int reluA,
    const float* __restrict__ B, int ldB,
    const float* __restrict__ bias,
    float* __restrict__ C, int ldC, int M,
    const int* __restrict__ row, const int* __restrict__ col,
    const float* __restrict__ P, const float* __restrict__ E0,
    const float* __restrict__ rot, const float* __restrict__ rotW,
    float* __restrict__ xsum, float* __restrict__ Hout)
{
    using namespace nvcuda;
    constexpr int BM = 128, BK = 32;
    constexpr int WN = BN / 2;           // warp col span
    constexpr int MT = 2, NT = WN / 16;
    constexpr int A_EL = BM * BK;        // 4096 halves per array
    constexpr int SMEM = 32768;          // >= tiles (24.5K/32K) and >= Cs (128x64x4)

    __shared__ __align__(16) char sraw[SMEM];
    __shared__ int sRow[BM], sCol[BM];
    __half* Ah = (__half*)sraw;
    __half* Al = Ah + A_EL;
    __half* Bh = Al + A_EL;
    __half* Bl = Bh + BK * BN;
    float*  Cs = (float*)sraw;           // 128 x 64 epilogue tile

    const int tid  = threadIdx.x;
    const int warp = tid >> 5;
    const int wm   = warp >> 1, wn = warp & 1;
    const int m0   = blockIdx.x * BM;
    const int K    = K0 + K1;

    if (EPI > 0 && tid < BM) {
        int e = m0 + tid;
        sRow[tid] = (e < M && row) ? row[e] : 0;
        sCol[tid] = (e < M && col) ? col[e] : 0;
    }

    wmma::fragment<wmma::accumulator, 16, 16, 16, float> acc[MT][NT];
#pragma unroll
    for (int mi = 0; mi < MT; mi++)
#pragma unroll
        for (int ni = 0; ni < NT; ni++) wmma::fill_fragment(acc[mi][ni], 0.f);

    for (int kb = 0; kb < K; kb += BK) {
        // ---- A tile: 128 x 32 fp32 -> exact fp16 split ----
        {
            const int r  = tid >> 1;
            const int m  = m0 + r;
            const int cb = (tid & 1) * 16;
#pragma unroll
            for (int q = 0; q < 4; q++) {
                const int c  = cb + q * 4;
                const int kk = kb + c;
                float4 v = make_float4(0.f, 0.f, 0.f, 0.f);
                if (m < M && kk < K) {
                    v = (kk < K0) ? *(const float4*)(A0 + (size_t)m * ldA0 + kk)
                                  : *(const float4*)(A1 + (size_t)m * ldA1 + (kk - K0));
                }
                if (reluA) {
                    v.x = fmaxf(v.x, 0.f); v.y = fmaxf(v.y, 0.f);
                    v.z = fmaxf(v.z, 0.f); v.w = fmaxf(v.w, 0.f);
                }
                hsplit_store4(Ah + r * BK + c, Al + r * BK + c, v);
            }
        }
        // ---- B tile: 32 x BN fp32 -> fp16 split ----
        {
            constexpr int JP = BN / 4;
#pragma unroll
            for (int t = 0; t < (BK * JP) / 256; t++) {
                const int idx = tid + t * 256;
                const int k = idx / JP, jc = idx % JP;
                const int kk = kb + k;
                float4 v = make_float4(0.f, 0.f, 0.f, 0.f);
                if (kk < K) v = *(const float4*)(B + (size_t)kk * ldB + jc * 4);
                hsplit_store4(Bh + k * BN + jc * 4, Bl + k * BN + jc * 4, v);
            }
        }
        __syncthreads();
#pragma unroll
        for (int ks = 0; ks < 2; ks++) {
            wmma::fragment<wmma::matrix_a, 16, 16, 16, __half, wmma::row_major> fah[MT], fal[MT];
#pragma unroll
            for (int mi = 0; mi < MT; mi++) {
                const int off = (wm * 32 + mi * 16) * BK + ks * 16;
                wmma::load_matrix_sync(fah[mi], Ah + off, BK);
                wmma::load_matrix_sync(fal[mi], Al + off, BK);
            }
#pragma unroll
            for (int ni = 0; ni < NT; ni++) {
                wmma::fragment<wmma::matrix_b, 16, 16, 16, __half, wmma::row_major> fbh, fbl;
                const int off = (ks * 16) * BN + wn * WN + ni * 16;
                wmma::load_matrix_sync(fbh, Bh + off, BN);
                wmma::load_matrix_sync(fbl, Bl + off, BN);
#pragma unroll
                for (int mi = 0; mi < MT; mi++) {
                    wmma::mma_sync(acc[mi][ni], fah[mi], fbh, acc[mi][ni]);
                    wmma::mma_sync(acc[mi][ni], fal[mi], fbh, acc[mi][ni]);
                    wmma::mma_sync(acc[mi][ni], fah[mi], fbl, acc[mi][ni]);
                }
            }
        }
        __syncthreads();
    }

    // ---- epilogue: Cs is 128 x 64; BN=64 one pass, BN=128 two passes ----
    constexpr int NPASS = BN / 64;
#pragma unroll
    for (int p = 0; p < NPASS; p++) {
        if (NPASS == 1 || wn == p) {
#pragma unroll
            for (int mi = 0; mi < MT; mi++)
#pragma unroll
                for (int ni = 0; ni < NT; ni++) {
                    const int cl = (NPASS == 1) ? (wn * WN + ni * 16) : (ni * 16);
                    wmma::store_matrix_sync(Cs + (wm * 32 + mi * 16) * 64 + cl,
                                            acc[mi][ni], 64, wmma::mem_row_major);
                }
        }
        __syncthreads();

        for (int idx = tid; idx < BM * 64; idx += 256) {
            const int i = idx >> 6, jl = idx & 63;
            const int m = m0 + i;
            if (m >= M) continue;
            const int j = p * 64 + jl;
            float v = Cs[idx];
            if (EPI == 0) {
                C[(size_t)m * ldC + j] = v;
            } else if (EPI == 1) {
                if (j >= 64) {
                    C[(size_t)m * ldC + j] = v;            // Ebig upper half
                } else {
                    const int r = sRow[i], c = sCol[i];
                    float h = v + P[r * 128 + j] + P[c * 128 + 64 + j] + bias[j];
#pragma unroll
                    for (int kk = 0; kk < 4; kk++)
                        h += rot[(size_t)m * 4 + kk] * rotW[kk * 64 + j];
                    Hout[(size_t)m * 64 + j] = fmaxf(h, 0.f);
                }
            } else if (EPI == 2 || EPI == 3) {
                const int r = sRow[i], c = sCol[i];
                float h = v + P[r * 128 + j] + P[c * 128 + 64 + j] + bias[j];
                if (EPI == 2) h += E0[(size_t)m * 128 + 64 + j];
                C[(size_t)m * 64 + j] = fmaxf(h, 0.f);
            } else { // EPI == 4
                v += bias[j];
                C[(size_t)m * 64 + j] = v;
                atomicAdd(&xsum[sRow[i] * 64 + j], v);
            }
        }
        if (p + 1 < NPASS) __syncthreads();
    }
}

// ---------------- misc kernels (R6 verbatim) ----------------
__global__ void pack_kernel(float* __restrict__ dst,
                            const float* __restrict__ srcA, int offA,
                            const float* __restrict__ srcB, int offB, int K)
{
    int idx = blockIdx.x * blockDim.x + threadIdx.x;
    if (idx >= K * 128) return;
    int k = idx >> 7, j = idx & 127;
    dst[idx] = (j < 64) ? srcA[(offA + k) * 64 + j]
                        : srcB[(offB + k) * 64 + (j - 64)];
}

__global__ void zero_f_kernel(float* p, long n)
{
    long i = (long)blockIdx.x * blockDim.x + threadIdx.x;
    if (i < n) p[i] = 0.f;
}
__global__ void zero_cnt_kernel()
{
    int i = blockIdx.x * blockDim.x + threadIdx.x;
    if (i < N_NODES) g_cnt[i] = 0;
}
__global__ void count_kernel(const int* __restrict__ row)
{
    int e = blockIdx.x * blockDim.x + threadIdx.x;
    if (e < N_EDGES) atomicAdd(&g_cnt[row[e]], 1);
}
__global__ void invdeg_kernel()
{
    int n = blockIdx.x * blockDim.x + threadIdx.x;
    if (n < N_NODES) g_inv[n] = 1.f / fmaxf((float)g_cnt[n], 1.f);
}
__global__ void finalize_kernel(float* __restrict__ x, int relu)
{
    int idx = blockIdx.x * blockDim.x + threadIdx.x;
    if (idx >= N_NODES * 64) return;
    int n = idx >> 6;
    float v = x[idx] * g_inv[n];
    x[idx] = relu ? fmaxf(v, 0.f) : v;
}

__global__ void node_head_kernel(const float* __restrict__ W,
                                 const float* __restrict__ b,
                                 float* __restrict__ out)
{
    int n = blockIdx.x * blockDim.x + threadIdx.x;
    if (n >= N_NODES) return;
    float y0 = b[0], y1 = b[1], y2 = b[2], y3 = b[3];
    const float* xr = g_x4 + (long)n * 64;
#pragma unroll 8
    for (int k = 0; k < 64; k++) {
        float xv = xr[k];
        y0 = fmaf(xv, W[k * 4 + 0], y0);
        y1 = fmaf(xv, W[k * 4 + 1], y1);
        y2 = fmaf(xv, W[k * 4 + 2], y2);
        y3 = fmaf(xv, W[k * 4 + 3], y3);
    }
    float s = y0 * y0 + y1 * y1 + y2 * y2 + y3 * y3;
    float r = 1.f / fmaxf(sqrtf(s), 1e-12f);
    out[n * 4 + 0] = y0 * r;
    out[n * 4 + 1] = y1 * r;
    out[n * 4 + 2] = y2 * r;
    out[n * 4 + 3] = y3 * r;
}

__global__ __launch_bounds__(256) void edge_head_kernel(
    const float* __restrict__ W1, const float* __restrict__ b1,
    const float* __restrict__ w2, const float* __restrict__ b2,
    float* __restrict__ out)
{
    __shared__ float sW[64 * 32];
    __shared__ float sb[32];
    int tid = threadIdx.x;
    for (int i = tid; i < 64 * 32; i += 256) sW[i] = W1[i];
    if (tid < 32) sb[tid] = b1[tid];
    __syncthreads();
    int lane = tid & 31, w = tid >> 5;
    int e = blockIdx.x * 8 + w;
    if (e >= E_HALF) return;
    const float* h0 = g_M4 + (long)e * 64;
    const float* h1 = g_M4 + (long)(e + E_HALF) * 64;
    float t = sb[lane];
#pragma unroll 8
    for (int k = 0; k < 64; k++) {
        float h = h0[k] + h1[k];
        t = fmaf(h, sW[k * 32 + lane], t);
    }
    float r = fmaxf(t, 0.f) * w2[lane];
#pragma unroll
    for (int off = 16; off; off >>= 1) r += __shfl_down_sync(0xffffffffu, r, off);
    if (lane == 0) out[e] = r + b2[0];
}

// ---------------- host orchestration ----------------
template <class T>
static void* symaddr_(T& s)
{
    void* p = nullptr;
    cudaGetSymbolAddress(&p, s);
    return p;
}
#define SYM(x) symaddr_(x)

extern "C" void kernel_launch(void* const* d_in, const int* in_sizes, int n_in,
                              void* d_out, int out_size)
{
    (void)in_sizes; (void)n_in; (void)out_size;
    const float* x_org = (const float*)d_in[0];
    const float* x_rot = (const float*)d_in[1];
    const int*   eidx  = (const int*)  d_in[2];
    const float* eattr = (const float*)d_in[3];
    const float* erot  = (const float*)d_in[4];
    const float* c1_w1 = (const float*)d_in[5];  const float* c1_b1 = (const float*)d_in[6];
    const float* c1_w2 = (const float*)d_in[7];  const float* c1_b2 = (const float*)d_in[8];
    const float* c2_w1 = (const float*)d_in[9];  const float* c2_b1 = (const float*)d_in[10];
    const float* c2_w2 = (const float*)d_in[11]; const float* c2_b2 = (const float*)d_in[12];
    const float* c3_w1 = (const float*)d_in[13]; const float* c3_b1 = (const float*)d_in[14];
    const float* c3_w2 = (const float*)d_in[15]; const float* c3_b2 = (const float*)d_in[16];
    const float* c4_w1 = (const float*)d_in[17]; const float* c4_b1 = (const float*)d_in[18];
    const float* c4_w2 = (const float*)d_in[19]; const float* c4_b2 = (const float*)d_in[20];
    const float* lin1_w = (const float*)d_in[21]; const float* lin1_b = (const float*)d_in[22];
    const float* efc_w1 = (const float*)d_in[23]; const float* efc_b1 = (const float*)d_in[24];
    const float* efc_w2 = (const float*)d_in[25]; const float* efc_b2 = (const float*)d_in[26];
    float* out = (float*)d_out;

    const int* row = eidx;
    const int* col = eidx + N_EDGES;

    float *P    = (float*)SYM(g_P);
    float *x1   = (float*)SYM(g_x1), *x2 = (float*)SYM(g_x2);
    float *x3   = (float*)SYM(g_x3), *x4 = (float*)SYM(g_x4);
    float *Ebig = (float*)SYM(g_Ebig), *H = (float*)SYM(g_H);
    float *M1   = (float*)SYM(g_M1), *M2 = (float*)SYM(g_M2);
    float *M3   = (float*)SYM(g_M3), *M4 = (float*)SYM(g_M4);
    float *W1n  = (float*)SYM(g_W1n), *Wbig = (float*)SYM(g_Wbig);
    float *W2n  = (float*)SYM(g_W2n);
    float *W3n  = (float*)SYM(g_W3n), *W4n = (float*)SYM(g_W4n);

    const int GE = N_EDGES / 128;              // 1000 blocks (BM=128)
    const int GN = (N_NODES + 127) / 128;      // 79
    const int ZB = (N_NODES * 64 + 255) / 256;
    const float* NF = nullptr;
    const int*   NI = nullptr;

    // --- prep (R6 order) ---
    pack_kernel<<<(260 * 128 + 255) / 256, 256>>>(W1n,  c1_w1, 0,   c1_w1, 260, 260);
    pack_kernel<<<(640 * 128 + 255) / 256, 256>>>(Wbig, c1_w1, 520, c2_w1, 128, 640);
    pack_kernel<<<(64  * 128 + 255) / 256, 256>>>(W2n,  c2_w1, 0,   c2_w1, 64,  64);
    pack_kernel<<<(128 * 128 + 255) / 256, 256>>>(W3n,  c3_w1, 0,   c3_w1, 128, 128);
    pack_kernel<<<(128 * 128 + 255) / 256, 256>>>(W4n,  c4_w1, 0,   c4_w1, 128, 128);
    zero_cnt_kernel<<<(N_NODES + 255) / 256, 256>>>();
    count_kernel<<<(N_EDGES + 255) / 256, 256>>>(row);
    invdeg_kernel<<<(N_NODES + 255) / 256, 256>>>();
    zero_f_kernel<<<ZB, 256>>>(x1, (long)N_NODES * 64);
    zero_f_kernel<<<ZB, 256>>>(x2, (long)N_NODES * 64);
    zero_f_kernel<<<ZB, 256>>>(x3, (long)N_NODES * 64);
    zero_f_kernel<<<ZB, 256>>>(x4, (long)N_NODES * 64);

    // ================= conv1 =================
    gemm_r<128, 0><<<GN, 256>>>(x_org, 256, 256, x_rot, 4, 4, 0,
                                W1n, 128, NF, P, 128, N_NODES,
                                NI, NI, NF, NF, NF, NF, nullptr, nullptr);
    gemm_r<128, 1><<<GE, 256>>>(eattr, 640, 640, NF, 0, 0, 0,
                                Wbig, 128, c1_b1, Ebig, 128, N_EDGES,
                                row, col, P, NF, erot, c1_w1 + 1160 * 64, nullptr, H);
    gemm_r<64, 4><<<GE, 256>>>(H, 64, 64, NF, 0, 0, 0,
                               c1_w2, 64, c1_b2, M1, 64, N_EDGES,
                               row, NI, NF, NF, NF, NF, x1, nullptr);
    finalize_kernel<<<ZB, 256>>>(x1, 0);

    // ================= conv2 =================
    gemm_r<128, 0><<<GN, 256>>>(x1, 64, 64, NF, 0, 0, 0,
                                W2n, 128, NF, P, 128, N_NODES,
                                NI, NI, NF, NF, NF, NF, nullptr, nullptr);
    gemm_r<64, 2><<<GE, 256>>>(M1, 64, 64, NF, 0, 0, 1,
                               c2_w1 + 768 * 64, 64, c2_b1, H, 64, N_EDGES,
                               row, col, P, Ebig, NF, NF, nullptr, nullptr);
    gemm_r<64, 4><<<GE, 256>>>(H, 64, 64, NF, 0, 0, 0,
                               c2_w2, 64, c2_b2, M2, 64, N_EDGES,
                               row, NI, NF, NF, NF, NF, x2, nullptr);
    finalize_kernel<<<ZB, 256>>>(x2, 1);

    // ================= conv3 =================
    gemm_r<128, 0><<<GN, 256>>>(x2, 64, 64, x1, 64, 64, 0,
                                W3n, 128, NF, P, 128, N_NODES,
                                NI, NI, NF, NF, NF, NF, nullptr, nullptr);
    gemm_r<64, 3><<<GE, 256>>>(M2, 64, 64, M1, 64, 64, 1,
                               c3_w1 + 256 * 64, 64, c3_b1, H, 64, N_EDGES,
                               row, col, P, NF, NF, NF, nullptr, nullptr);
    gemm_r<64, 4><<<GE, 256>>>(H, 64, 64, NF, 0, 0, 0,
                               c3_w2, 64, c3_b2, M3, 64, N_EDGES,
                               row, NI, NF, NF, NF, NF, x3, nullptr);
    finalize_kernel<<<ZB, 256>>>(x3, 1);

    // ================= conv4 =================
    gemm_r<128, 0><<<GN, 256>>>(x3, 64, 64, x2, 64, 64, 0,
                                W4n, 128, NF, P, 128, N_NODES,
                                NI, NI, NF, NF, NF, NF, nullptr, nullptr);
    gemm_r<64, 3><<<GE, 256>>>(M3, 64, 64, M2, 64, 64, 1,
                               c4_w1 + 256 * 64, 64, c4_b1, H, 64, N_EDGES,
                               row, col, P, NF, NF, NF, nullptr, nullptr);
    gemm_r<64, 4><<<GE, 256>>>(H, 64, 64, NF, 0, 0, 0,
                               c4_w2, 64, c4_b2, M4, 64, N_EDGES,
                               row, NI, NF, NF, NF, NF, x4, nullptr);
    finalize_kernel<<<ZB, 256>>>(x4, 1);

    // ================= heads =================
    node_head_kernel<<<(N_NODES + 127) / 128, 128>>>(lin1_w, lin1_b, out);
    edge_head_kernel<<<(E_HALF + 7) / 8, 256>>>(efc_w1, efc_b1, efc_w2, efc_b2,
                                                out + N_NODES * 4);
}

// round 17
// speedup vs baseline: 1.1044x; 1.0548x over previous
#include <cuda_runtime.h>
#include <cuda_fp16.h>
#include <mma.h>
#include <math.h>
#include <stdint.h>

#define N_NODES 10000
#define N_EDGES 128000
#define E_HALF  64000

// ---------------- scratch (device globals; no allocations allowed) ----------------
__device__ float g_P   [N_NODES*128];
__device__ float g_x1  [N_NODES*64];
__device__ float g_x2  [N_NODES*64];
__device__ float g_x3  [N_NODES*64];
__device__ float g_x4  [N_NODES*64];
__device__ float g_Ebig[(size_t)N_EDGES*128];
__device__ float g_M1  [(size_t)N_EDGES*64];
__device__ float g_M2  [(size_t)N_EDGES*64];
__device__ float g_M3  [(size_t)N_EDGES*64];
__device__ float g_M4  [(size_t)N_EDGES*64];
__device__ float g_H   [(size_t)N_EDGES*64];
__device__ float g_W1n [260*128];
__device__ float g_Wbig[640*128];
__device__ float g_W2n [64*128];
__device__ float g_W3n [128*128];
__device__ float g_W4n [128*128];
__device__ float g_inv [N_NODES];
__device__ int   g_cnt [N_NODES];

// ---------------- fp16 split helpers ----------------
__device__ __forceinline__ void hsplit_store4(__half* ph, __half* pl, float4 v)
{
    float vv[4] = { v.x, v.y, v.z, v.w };
#pragma unroll
    for (int i = 0; i < 4; i++) {
        __half h = __float2half_rn(vv[i]);
        ph[i] = h;
        pl[i] = __float2half_rn(vv[i] - __half2float(h));
    }
}
__device__ __forceinline__ void hcvt_store4(__half* ph, float4 v)
{
    ph[0] = __float2half_rn(v.x);
    ph[1] = __float2half_rn(v.y);
    ph[2] = __float2half_rn(v.z);
    ph[3] = __float2half_rn(v.w);
}

// =====================================================================
// Split-fp16 WMMA GEMM (R6 shape: BM=64, BK=32, warps 2x4).
//   TERMS=3: C = Ah@Bh + Al@Bh + Ah@Bl   (A exact split, B exact split)
//   TERMS=2: C = Ah@Bh + Ah@Bl           (A fp16-rounded, B exact split)
// EPI modes (identical to R6):
//   0: C = acc                                          (node P GEMMs)
//   1: conv1-big: j>=64 -> C(=Ebig, ldC=128); j<64 -> Hout = relu(acc+Pgather+bias+rot@rotW)
//   2: C = relu(acc + Ebig[:,64+j] + Pgather + bias)    (conv2 hidden)
//   3: C = relu(acc + Pgather + bias)                   (conv3/4 hidden)
//   4: v = acc + bias; C = v; atomicAdd(xsum[row], v)   (M GEMM + scatter)
// =====================================================================
template<int BN, int EPI, int TERMS>
__global__ __launch_bounds__(256) void gemm_t(
    const float* __restrict__ A0, int ldA0, int K0,
    const float* __restrict__ A1, int ldA1, int K1, int reluA,
    const float* __restrict__ B, int ldB,
    const float* __restrict__ bias,
    float* __restrict__ C, int ldC, int M,
    const int* __restrict__ row, const int* __restrict__ col,
    const float* __restrict__ P, const float* __restrict__ E0,
    const float* __restrict__ rot, const float* __restrict__ rotW,
    float* __restrict__ xsum, float* __restrict__ Hout)
{
    using namespace nvcuda;
    constexpr int BM = 64, BK = 32;
    constexpr int WN = BN / 4;
    constexpr int MT = 2, NT = WN / 16;
    constexpr int NA = (TERMS == 3) ? 2 : 1;                 // A arrays
    constexpr int TILE_BYTES = (NA * BM * BK + 2 * BK * BN) * 2;
    constexpr int CS_BYTES   = BM * BN * 4;
    constexpr int SMEM_BYTES = TILE_BYTES > CS_BYTES ? TILE_BYTES : CS_BYTES;

    __shared__ __align__(16) char sraw[SMEM_BYTES];
    __shared__ int sRow[BM], sCol[BM];
    __half* Ah = (__half*)sraw;
    __half* Al = Ah + BM * BK;                               // valid only TERMS==3
    __half* Bh = Ah + NA * BM * BK;
    __half* Bl = Bh + BK * BN;
    float* Cs = (float*)sraw;

    const int tid  = threadIdx.x;
    const int warp = tid >> 5;
    const int wm   = warp >> 2, wn = warp & 3;
    const int m0   = blockIdx.x * BM;
    const int K    = K0 + K1;

    if (EPI > 0 && tid < BM) {
        int e = m0 + tid;
        sRow[tid] = (e < M && row) ? row[e] : 0;
        sCol[tid] = (e < M && col) ? col[e] : 0;
    }

    wmma::fragment<wmma::accumulator, 16, 16, 16, float> acc[MT][NT];
#pragma unroll
    for (int mi = 0; mi < MT; mi++)
#pragma unroll
        for (int ni = 0; ni < NT; ni++) wmma::fill_fragment(acc[mi][ni], 0.f);

    for (int kb = 0; kb < K; kb += BK) {
        // ---- A tile: 64 x 32 fp32 -> fp16 (split if TERMS==3) ----
        {
            const int r  = tid >> 2;
            const int m  = m0 + r;
            const int cb = (tid & 3) * 8;
#pragma unroll
            for (int q = 0; q < 2; q++) {
                const int c  = cb + q * 4;
                const int kk = kb + c;
                float4 v = make_float4(0.f, 0.f, 0.f, 0.f);
                if (m < M && kk < K) {
                    v = (kk < K0) ? *(const float4*)(A0 + (size_t)m * ldA0 + kk)
                                  : *(const float4*)(A1 + (size_t)m * ldA1 + (kk - K0));
                }
                if (reluA) {
                    v.x = fmaxf(v.x, 0.f); v.y = fmaxf(v.y, 0.f);
                    v.z = fmaxf(v.z, 0.f); v.w = fmaxf(v.w, 0.f);
                }
                if (TERMS == 3) hsplit_store4(Ah + r * BK + c, Al + r * BK + c, v);
                else            hcvt_store4(Ah + r * BK + c, v);
            }
        }
        // ---- B tile: 32 x BN fp32 -> exact fp16 split ----
        {
            constexpr int JP = BN / 4;
#pragma unroll
            for (int idx = tid; idx < BK * JP; idx += 256) {
                const int k = idx / JP, jc = idx % JP;
                const int kk = kb + k;
                float4 v = make_float4(0.f, 0.f, 0.f, 0.f);
                if (kk < K) v = *(const float4*)(B + (size_t)kk * ldB + jc * 4);
                hsplit_store4(Bh + k * BN + jc * 4, Bl + k * BN + jc * 4, v);
            }
        }
        __syncthreads();
#pragma unroll
        for (int ks = 0; ks < 2; ks++) {
            wmma::fragment<wmma::matrix_a, 16, 16, 16, __half, wmma::row_major> fah[MT], fal[MT];
            wmma::fragment<wmma::matrix_b, 16, 16, 16, __half, wmma::row_major> fbh[NT], fbl[NT];
#pragma unroll
            for (int mi = 0; mi < MT; mi++) {
                const int off = (wm * 32 + mi * 16) * BK + ks * 16;
                wmma::load_matrix_sync(fah[mi], Ah + off, BK);
                if (TERMS == 3) wmma::load_matrix_sync(fal[mi], Al + off, BK);
            }
#pragma unroll
            for (int ni = 0; ni < NT; ni++) {
                const int off = (ks * 16) * BN + wn * WN + ni * 16;
                wmma::load_matrix_sync(fbh[ni], Bh + off, BN);
                wmma::load_matrix_sync(fbl[ni], Bl + off, BN);
            }
#pragma unroll
            for (int mi = 0; mi < MT; mi++)
#pragma unroll
                for (int ni = 0; ni < NT; ni++) {
                    wmma::mma_sync(acc[mi][ni], fah[mi], fbh[ni], acc[mi][ni]);
                    if (TERMS == 3) wmma::mma_sync(acc[mi][ni], fal[mi], fbh[ni], acc[mi][ni]);
                    wmma::mma_sync(acc[mi][ni], fah[mi], fbl[ni], acc[mi][ni]);
                }
        }
        __syncthreads();
    }

    // ---- epilogue via smem C tile (tiles dead; reuse sraw) ----
#pragma unroll
    for (int mi = 0; mi < MT; mi++)
#pragma unroll
        for (int ni = 0; ni < NT; ni++)
            wmma::store_matrix_sync(Cs + (wm * 32 + mi * 16) * BN + wn * WN + ni * 16,
                                    acc[mi][ni], BN, wmma::mem_row_major);
    __syncthreads();

    for (int idx = tid; idx < BM * BN; idx += 256) {
        const int i = idx / BN, j = idx - i * BN;
        const int m = m0 + i;
        if (m >= M) continue;
        float v = Cs[idx];
        if (EPI == 0) {
            C[(size_t)m * ldC + j] = v;
        } else if (EPI == 1) {
            if (j >= 64) {
                C[(size_t)m * ldC + j] = v;                 // Ebig upper half
            } else {
                const int r = sRow[i], c = sCol[i];
                float h = v + P[r * 128 + j] + P[c * 128 + 64 + j] + bias[j];
#pragma unroll
                for (int kk = 0; kk < 4; kk++)
                    h += rot[(size_t)m * 4 + kk] * rotW[kk * 64 + j];
                Hout[(size_t)m * 64 + j] = fmaxf(h, 0.f);
            }
        } else if (EPI == 2 || EPI == 3) {
            const int r = sRow[i], c = sCol[i];
            float h = v + P[r * 128 + j] + P[c * 128 + 64 + j] + bias[j];
            if (EPI == 2) h += E0[(size_t)m * 128 + 64 + j];
            C[(size_t)m * 64 + j] = fmaxf(h, 0.f);
        } else { // EPI == 4
            v += bias[j];
            C[(size_t)m * 64 + j] = v;
            atomicAdd(&xsum[sRow[i] * 64 + j], v);
        }
    }
}

// ---------------- misc kernels ----------------
__global__ void pack_kernel(float* __restrict__ dst,
                            const float* __restrict__ srcA, int offA,
                            const float* __restrict__ srcB, int offB, int K)
{
    int idx = blockIdx.x * blockDim.x + threadIdx.x;
    if (idx >= K * 128) return;
    int k = idx >> 7, j = idx & 127;
    dst[idx] = (j < 64) ? srcA[(offA + k) * 64 + j]
                        : srcB[(offB + k) * 64 + (j - 64)];
}

// one launch: zero x1..x4 (N*64 each) and cnt (N)
__global__ void zero_all_kernel()
{
    int idx = blockIdx.x * blockDim.x + threadIdx.x;
    const int NX = N_NODES * 64;
    if (idx < NX) {
        g_x1[idx] = 0.f; g_x2[idx] = 0.f; g_x3[idx] = 0.f; g_x4[idx] = 0.f;
        if (idx < N_NODES) g_cnt[idx] = 0;
    }
}
__global__ void count_kernel(const int* __restrict__ row)
{
    int e = blockIdx.x * blockDim.x + threadIdx.x;
    if (e < N_EDGES) atomicAdd(&g_cnt[row[e]], 1);
}
__global__ void invdeg_kernel()
{
    int n = blockIdx.x * blockDim.x + threadIdx.x;
    if (n < N_NODES) g_inv[n] = 1.f / fmaxf((float)g_cnt[n], 1.f);
}
__global__ void finalize_kernel(float* __restrict__ x, int relu)
{
    int idx = blockIdx.x * blockDim.x + threadIdx.x;
    if (idx >= N_NODES * 64) return;
    int n = idx >> 6;
    float v = x[idx] * g_inv[n];
    x[idx] = relu ? fmaxf(v, 0.f) : v;
}

__global__ void node_head_kernel(const float* __restrict__ W,
                                 const float* __restrict__ b,
                                 float* __restrict__ out)
{
    int n = blockIdx.x * blockDim.x + threadIdx.x;
    if (n >= N_NODES) return;
    float y0 = b[0], y1 = b[1], y2 = b[2], y3 = b[3];
    const float* xr = g_x4 + (long)n * 64;
#pragma unroll 8
    for (int k = 0; k < 64; k++) {
        float xv = xr[k];
        y0 = fmaf(xv, W[k * 4 + 0], y0);
        y1 = fmaf(xv, W[k * 4 + 1], y1);
        y2 = fmaf(xv, W[k * 4 + 2], y2);
        y3 = fmaf(xv, W[k * 4 + 3], y3);
    }
    float s = y0 * y0 + y1 * y1 + y2 * y2 + y3 * y3;
    float r = 1.f / fmaxf(sqrtf(s), 1e-12f);
    out[n * 4 + 0] = y0 * r;
    out[n * 4 + 1] = y1 * r;
    out[n * 4 + 2] = y2 * r;
    out[n * 4 + 3] = y3 * r;
}

__global__ __launch_bounds__(256) void edge_head_kernel(
    const float* __restrict__ W1, const float* __restrict__ b1,
    const float* __restrict__ w2, const float* __restrict__ b2,
    float* __restrict__ out)
{
    __shared__ float sW[64 * 32];
    __shared__ float sb[32];
    int tid = threadIdx.x;
    for (int i = tid; i < 64 * 32; i += 256) sW[i] = W1[i];
    if (tid < 32) sb[tid] = b1[tid];
    __syncthreads();
    int lane = tid & 31, w = tid >> 5;
    int e = blockIdx.x * 8 + w;
    if (e >= E_HALF) return;
    const float* h0 = g_M4 + (long)e * 64;
    const float* h1 = g_M4 + (long)(e + E_HALF) * 64;
    float t = sb[lane];
#pragma unroll 8
    for (int k = 0; k < 64; k++) {
        float h = h0[k] + h1[k];
        t = fmaf(h, sW[k * 32 + lane], t);
    }
    float r = fmaxf(t, 0.f) * w2[lane];
#pragma unroll
    for (int off = 16; off; off >>= 1) r += __shfl_down_sync(0xffffffffu, r, off);
    if (lane == 0) out[e] = r + b2[0];
}

// ---------------- host orchestration (R6 verbatim) ----------------
template <class T>
static void* symaddr_(T& s)
{
    void* p = nullptr;
    cudaGetSymbolAddress(&p, s);
    return p;
}
#define SYM(x) symaddr_(x)

extern "C" void kernel_launch(void* const* d_in, const int* in_sizes, int n_in,
                              void* d_out, int out_size)
{
    (void)in_sizes; (void)n_in; (void)out_size;
    const float* x_org = (const float*)d_in[0];
    const float* x_rot = (const float*)d_in[1];
    const int*   eidx  = (const int*)  d_in[2];
    const float* eattr = (const float*)d_in[3];
    const float* erot  = (const float*)d_in[4];
    const float* c1_w1 = (const float*)d_in[5];  const float* c1_b1 = (const float*)d_in[6];
    const float* c1_w2 = (const float*)d_in[7];  const float* c1_b2 = (const float*)d_in[8];
    const float* c2_w1 = (const float*)d_in[9];  const float* c2_b1 = (const float*)d_in[10];
    const float* c2_w2 = (const float*)d_in[11]; const float* c2_b2 = (const float*)d_in[12];
    const float* c3_w1 = (const float*)d_in[13]; const float* c3_b1 = (const float*)d_in[14];
    const float* c3_w2 = (const float*)d_in[15]; const float* c3_b2 = (const float*)d_in[16];
    const float* c4_w1 = (const float*)d_in[17]; const float* c4_b1 = (const float*)d_in[18];
    const float* c4_w2 = (const float*)d_in[19]; const float* c4_b2 = (const float*)d_in[20];
    const float* lin1_w = (const float*)d_in[21]; const float* lin1_b = (const float*)d_in[22];
    const float* efc_w1 = (const float*)d_in[23]; const float* efc_b1 = (const float*)d_in[24];
    const float* efc_w2 = (const float*)d_in[25]; const float* efc_b2 = (const float*)d_in[26];
    float* out = (float*)d_out;

    const int* row = eidx;
    const int* col = eidx + N_EDGES;

    float *P    = (float*)SYM(g_P);
    float *x1   = (float*)SYM(g_x1), *x2 = (float*)SYM(g_x2);
    float *x3   = (float*)SYM(g_x3), *x4 = (float*)SYM(g_x4);
    float *Ebig = (float*)SYM(g_Ebig), *H = (float*)SYM(g_H);
    float *M1   = (float*)SYM(g_M1), *M2 = (float*)SYM(g_M2);
    float *M3   = (float*)SYM(g_M3), *M4 = (float*)SYM(g_M4);
    float *W1n  = (float*)SYM(g_W1n), *Wbig = (float*)SYM(g_Wbig);
    float *W2n  = (float*)SYM(g_W2n);
    float *W3n  = (float*)SYM(g_W3n), *W4n = (float*)SYM(g_W4n);

    const int GE = N_EDGES / 64;               // 2000
    const int GN = (N_NODES + 63) / 64;        // 157
    const int ZB = (N_NODES * 64 + 255) / 256;
    const float* NF = nullptr;
    const int*   NI = nullptr;

    // --- prep ---
    pack_kernel<<<(260 * 128 + 255) / 256, 256>>>(W1n,  c1_w1, 0,   c1_w1, 260, 260);
    pack_kernel<<<(640 * 128 + 255) / 256, 256>>>(Wbig, c1_w1, 520, c2_w1, 128, 640);
    pack_kernel<<<(64  * 128 + 255) / 256, 256>>>(W2n,  c2_w1, 0,   c2_w1, 64,  64);
    pack_kernel<<<(128 * 128 + 255) / 256, 256>>>(W3n,  c3_w1, 0,   c3_w1, 128, 128);
    pack_kernel<<<(128 * 128 + 255) / 256, 256>>>(W4n,  c4_w1, 0,   c4_w1, 128, 128);
    zero_all_kernel<<<ZB, 256>>>();
    count_kernel<<<(N_EDGES + 255) / 256, 256>>>(row);
    invdeg_kernel<<<(N_NODES + 255) / 256, 256>>>();

    // ================= conv1 =================
    gemm_t<128, 0, 3><<<GN, 256>>>(x_org, 256, 256, x_rot, 4, 4, 0,
                                   W1n, 128, NF, P, 128, N_NODES,
                                   NI, NI, NF, NF, NF, NF, nullptr, nullptr);
    // BIG fused edge GEMM — TERMS=2 (eattr fp16-rounded, weights exact split)
    gemm_t<128, 1, 2><<<GE, 256>>>(eattr, 640, 640, NF, 0, 0, 0,
                                   Wbig, 128, c1_b1, Ebig, 128, N_EDGES,
                                   row, col, P, NF, erot, c1_w1 + 1160 * 64, nullptr, H);
    gemm_t<64, 4, 3><<<GE, 256>>>(H, 64, 64, NF, 0, 0, 0,
                                  c1_w2, 64, c1_b2, M1, 64, N_EDGES,
                                  row, NI, NF, NF, NF, NF, x1, nullptr);
    finalize_kernel<<<ZB, 256>>>(x1, 0);

    // ================= conv2 =================
    gemm_t<128, 0, 3><<<GN, 256>>>(x1, 64, 64, NF, 0, 0, 0,
                                   W2n, 128, NF, P, 128, N_NODES,
                                   NI, NI, NF, NF, NF, NF, nullptr, nullptr);
    gemm_t<64, 2, 3><<<GE, 256>>>(M1, 64, 64, NF, 0, 0, 1,
                                  c2_w1 + 768 * 64, 64, c2_b1, H, 64, N_EDGES,
                                  row, col, P, Ebig, NF, NF, nullptr, nullptr);
    gemm_t<64, 4, 3><<<GE, 256>>>(H, 64, 64, NF, 0, 0, 0,
                                  c2_w2, 64, c2_b2, M2, 64, N_EDGES,
                                  row, NI, NF, NF, NF, NF, x2, nullptr);
    finalize_kernel<<<ZB, 256>>>(x2, 1);

    // ================= conv3 =================
    gemm_t<128, 0, 3><<<GN, 256>>>(x2, 64, 64, x1, 64, 64, 0,
                                   W3n, 128, NF, P, 128, N_NODES,
                                   NI, NI, NF, NF, NF, NF, nullptr, nullptr);
    gemm_t<64, 3, 3><<<GE, 256>>>(M2, 64, 64, M1, 64, 64, 1,
                                  c3_w1 + 256 * 64, 64, c3_b1, H, 64, N_EDGES,
                                  row, col, P, NF, NF, NF, nullptr, nullptr);
    gemm_t<64, 4, 3><<<GE, 256>>>(H, 64, 64, NF, 0, 0, 0,
                                  c3_w2, 64, c3_b2, M3, 64, N_EDGES,
                                  row, NI, NF, NF, NF, NF, x3, nullptr);
    finalize_kernel<<<ZB, 256>>>(x3, 1);

    // ================= conv4 =================
    gemm_t<128, 0, 3><<<GN, 256>>>(x3, 64, 64, x2, 64, 64, 0,
                                   W4n, 128, NF, P, 128, N_NODES,
                                   NI, NI, NF, NF, NF, NF, nullptr, nullptr);
    gemm_t<64, 3, 3><<<GE, 256>>>(M3, 64, 64, M2, 64, 64, 1,
                                  c4_w1 + 256 * 64, 64, c4_b1, H, 64, N_EDGES,
                                  row, col, P, NF, NF, NF, nullptr, nullptr);
    gemm_t<64, 4, 3><<<GE, 256>>>(H, 64, 64, NF, 0, 0, 0,
                                  c4_w2, 64, c4_b2, M4, 64, N_EDGES,
                                  row, NI, NF, NF, NF, NF, x4, nullptr);
    finalize_kernel<<<ZB, 256>>>(x4, 1);

    // ================= heads =================
    node_head_kernel<<<(N_NODES + 127) / 128, 128>>>(lin1_w, lin1_b, out);
    edge_head_kernel<<<(E_HALF + 7) / 8, 256>>>(efc_w1, efc_b1, efc_w2, efc_b2,
                                                out + N_NODES * 4);
}